// round 11
// baseline (speedup 1.0000x reference)
#include <cuda_runtime.h>
#include <cstdint>

// DepthDCOp: out[n,c,h,w] = sum_{kh,kw} x_pad[n,c,h+kh-1,w+kw-1] * ker[n,0,kh*3+kw,h,w]
// N=8, C=256, H=64, W=64, K=3, dilation=1.

#define N_ 8
#define C_ 256
#define H_ 64
#define W_ 64
#define HW_ (H_ * W_)
#define HSTRIP 16    // h rows per block

__global__ __launch_bounds__(256, 5)
void ddf_kernel(const float* __restrict__ x,
                const float* __restrict__ ker,
                float* __restrict__ out)
{
    // grid = (N*H/HSTRIP, C/16) = (32, 16) -> 512 blocks; 5/SM x 148 = 740 slots
    // => single resident wave.
    const int bx    = blockIdx.x;
    const int n     = bx >> 2;            // / (H_/HSTRIP)
    const int h0    = (bx & 3) * HSTRIP;
    const int tx    = threadIdx.x;        // 0..15 -> w quad
    const int ty    = threadIdx.y;        // 0..15 -> channel
    const int tid   = ty * 16 + tx;
    const int w0    = tx << 2;
    const int c     = (blockIdx.y << 4) + ty;

    // ---- Stage ALL weights for this (n, 16-row strip): 16 x 9 x 64 fl = 36 KB ----
    __shared__ float4 sk[HSTRIP][9][16];   // [hh][tap][w-quad]
    {
        const float4* kp = reinterpret_cast<const float4*>(ker + (size_t)n * 9 * HW_);
        #pragma unroll
        for (int i = tid; i < HSTRIP * 9 * 16; i += 256) {
            const int hh  = i / 144;
            const int rem = i - hh * 144;
            const int t   = rem >> 4;
            const int q   = rem & 15;
            sk[hh][t][q] = kp[(size_t)t * (HW_ / 4) + (size_t)(h0 + hh) * 16 + q];
        }
    }

    const float* xb = x + (((size_t)n * C_ + c) * H_) * W_ + w0;
    const float4 z4 = make_float4(0.f, 0.f, 0.f, 0.f);
    const bool lok = (tx > 0), rok = (tx < 15);

    struct Row { float4 b; float lh, rh; };

    auto load_raw = [&](int hh) -> float4 {
        const bool ok = (hh >= 0) & (hh < H_);
        return ok ? *reinterpret_cast<const float4*>(xb + (size_t)hh * W_) : z4;
    };
    auto finish_row = [&](float4 raw, Row& r) {
        r.b  = raw;
        float l  = __shfl_up_sync(0xffffffffu,  raw.w, 1, 16);
        float rr = __shfl_down_sync(0xffffffffu, raw.x, 1, 16);
        r.lh = lok ? l  : 0.f;
        r.rh = rok ? rr : 0.f;
    };

    // Prime: rows h0-1..h0+1 into the window, rows h0+2 in flight (distance-2 ring).
    float4 raw0 = load_raw(h0 - 1);
    float4 raw1 = load_raw(h0);
    float4 raw2 = load_raw(h0 + 1);
    float4 ring[2];
    ring[0] = load_raw(h0 + 2);          // consumed at end of step 0

    __syncthreads();   // weights staged; all 4 LDGs above remain in flight

    Row rbuf[3];
    finish_row(raw0, rbuf[0]);
    finish_row(raw1, rbuf[1]);
    finish_row(raw2, rbuf[2]);

    float* ob = out + (((size_t)n * C_ + c) * H_ + h0) * W_ + w0;

    #pragma unroll
    for (int s = 0; s < HSTRIP; s++) {
        // Prefetch row h0+s+3 (consumed at end of step s+1): distance-2 cover.
        if (s < HSTRIP - 2) ring[(s + 1) & 1] = load_raw(h0 + s + 3);

        const Row& top = rbuf[ s      % 3];
        const Row& mid = rbuf[(s + 1) % 3];
        const Row& bot = rbuf[(s + 2) % 3];

        float acc0 = 0.f, acc1 = 0.f, acc2 = 0.f, acc3 = 0.f;

        #pragma unroll
        for (int kh = 0; kh < 3; kh++) {
            const Row& rr = (kh == 0) ? top : (kh == 1) ? mid : bot;
            const float win[6] = { rr.lh, rr.b.x, rr.b.y, rr.b.z, rr.b.w, rr.rh };
            #pragma unroll
            for (int kw = 0; kw < 3; kw++) {
                const float4 kvt = sk[s][kh * 3 + kw][tx];
                acc0 = fmaf(kvt.x, win[kw + 0], acc0);
                acc1 = fmaf(kvt.y, win[kw + 1], acc1);
                acc2 = fmaf(kvt.z, win[kw + 2], acc2);
                acc3 = fmaf(kvt.w, win[kw + 3], acc3);
            }
        }

        float4 o; o.x = acc0; o.y = acc1; o.z = acc2; o.w = acc3;
        *reinterpret_cast<float4*>(ob + (size_t)s * W_) = o;

        // Rotate: row h0+s+2 (in flight since step s-1) replaces the retired slot.
        if (s < HSTRIP - 1) finish_row(ring[s & 1], rbuf[s % 3]);
    }
}

extern "C" void kernel_launch(void* const* d_in, const int* in_sizes, int n_in,
                              void* d_out, int out_size)
{
    const float* x   = (const float*)d_in[0];   // [8,256,64,64]
    const float* ker = (const float*)d_in[1];   // [8,1,9,64,64]
    float* out = (float*)d_out;                 // [8,256,64,64]

    dim3 block(16, 16);
    dim3 grid(N_ * (H_ / HSTRIP), C_ / 16);     // (32, 16) = 512 blocks
    ddf_kernel<<<grid, block>>>(x, ker, out);
}

// round 15
// speedup vs baseline: 1.3996x; 1.3996x over previous
#include <cuda_runtime.h>
#include <cstdint>

// DepthDCOp: out[n,c,h,w] = sum_{kh,kw} x_pad[n,c,h+kh-1,w+kw-1] * ker[n,0,kh*3+kw,h,w]
// N=8, C=256, H=64, W=64, K=3, dilation=1.

#define N_ 8
#define C_ 256
#define H_ 64
#define W_ 64
#define HW_ (H_ * W_)
#define CPT 2        // channels per thread
#define HSTRIP 8     // h rows per block
#define TY_ 8        // channel pairs per block (16 channels)

__global__ __launch_bounds__(128, 7)
void ddf_kernel(const float* __restrict__ x,
                const float* __restrict__ ker,
                float* __restrict__ out)
{
    // grid = (N*H/HSTRIP, C/(TY_*CPT)) = (64, 16) -> 1024 blocks.
    // 7 blocks/SM x 148 SMs = 1036 slots >= 1024: one wave, 7-vs-6.92 balance.
    const int bx    = blockIdx.x;
    const int n     = bx >> 3;            // / (H_/HSTRIP)
    const int h0    = (bx & 7) * HSTRIP;
    const int tx    = threadIdx.x;        // 0..15 -> w quad
    const int ty    = threadIdx.y;        // 0..7  -> channel pair
    const int tid   = ty * 16 + tx;
    const int w0    = tx << 2;
    const int c0    = (blockIdx.y << 4) + (ty << 1);   // 16 channels per block

    // ---- Stage ALL weights for this (n, h-strip): 8 x 9 x 64 floats = 18 KB ----
    __shared__ float4 sk[HSTRIP][9][16];   // [hh][tap][w-quad]
    {
        const float4* kp = reinterpret_cast<const float4*>(ker + (size_t)n * 9 * HW_);
        #pragma unroll
        for (int i = tid; i < HSTRIP * 9 * 16; i += 128) {
            const int hh  = i / 144;
            const int rem = i - hh * 144;
            const int t   = rem >> 4;
            const int q   = rem & 15;
            sk[hh][t][q] = kp[(size_t)t * (HW_ / 4) + (size_t)(h0 + hh) * 16 + q];
        }
    }

    const float* xb = x + (((size_t)n * C_ + c0) * H_) * W_ + w0;
    const float4 z4 = make_float4(0.f, 0.f, 0.f, 0.f);
    const bool lok = (tx > 0), rok = (tx < 15);

    struct Row { float4 b[CPT]; float lh[CPT], rh[CPT]; };

    auto load_raw = [&](int hh, float4 raw[CPT]) {
        const bool ok = (hh >= 0) & (hh < H_);
        #pragma unroll
        for (int ci = 0; ci < CPT; ci++)
            raw[ci] = ok ? *reinterpret_cast<const float4*>(
                               xb + (size_t)ci * HW_ + (size_t)hh * W_)
                         : z4;
    };
    auto finish_row = [&](const float4 raw[CPT], Row& r) {
        #pragma unroll
        for (int ci = 0; ci < CPT; ci++) {
            r.b[ci]  = raw[ci];
            float l  = __shfl_up_sync(0xffffffffu,  raw[ci].w, 1, 16);
            float rr = __shfl_down_sync(0xffffffffu, raw[ci].x, 1, 16);
            r.lh[ci] = lok ? l  : 0.f;
            r.rh[ci] = rok ? rr : 0.f;
        }
    };

    // Prime window rows h0-1..h0+1 and ring rows h0+2, h0+3 (10 LDG.128 in flight).
    float4 raw0[CPT], raw1[CPT], raw2[CPT];
    float4 ring[3][CPT];
    load_raw(h0 - 1, raw0);
    load_raw(h0,     raw1);
    load_raw(h0 + 1, raw2);
    load_raw(h0 + 2, ring[0]);
    load_raw(h0 + 3, ring[1]);

    __syncthreads();   // weights staged; all x loads above remain in flight

    Row rbuf[3];
    finish_row(raw0, rbuf[0]);
    finish_row(raw1, rbuf[1]);
    finish_row(raw2, rbuf[2]);

    float* ob = out + (((size_t)n * C_ + c0) * H_ + h0) * W_ + w0;

    #pragma unroll
    for (int s = 0; s < HSTRIP; s++) {
        // Distance-2 prefetch: row h0+s+4 issued now, consumed end of step s+2.
        if (s < HSTRIP - 3) load_raw(h0 + s + 4, ring[(s + 2) % 3]);

        const Row& top = rbuf[ s      % 3];
        const Row& mid = rbuf[(s + 1) % 3];
        const Row& bot = rbuf[(s + 2) % 3];

        float acc[CPT][4];
        #pragma unroll
        for (int ci = 0; ci < CPT; ci++)
            #pragma unroll
            for (int j = 0; j < 4; j++) acc[ci][j] = 0.f;

        #pragma unroll
        for (int kh = 0; kh < 3; kh++) {
            const Row& rr = (kh == 0) ? top : (kh == 1) ? mid : bot;
            #pragma unroll
            for (int kw = 0; kw < 3; kw++) {
                const float4 kvt = sk[s][kh * 3 + kw][tx];
                #pragma unroll
                for (int ci = 0; ci < CPT; ci++) {
                    const float win[6] = { rr.lh[ci], rr.b[ci].x, rr.b[ci].y,
                                           rr.b[ci].z, rr.b[ci].w, rr.rh[ci] };
                    acc[ci][0] = fmaf(kvt.x, win[kw + 0], acc[ci][0]);
                    acc[ci][1] = fmaf(kvt.y, win[kw + 1], acc[ci][1]);
                    acc[ci][2] = fmaf(kvt.z, win[kw + 2], acc[ci][2]);
                    acc[ci][3] = fmaf(kvt.w, win[kw + 3], acc[ci][3]);
                }
            }
        }

        #pragma unroll
        for (int ci = 0; ci < CPT; ci++) {
            float4 o;
            o.x = acc[ci][0]; o.y = acc[ci][1]; o.z = acc[ci][2]; o.w = acc[ci][3];
            *reinterpret_cast<float4*>(ob + (size_t)ci * HW_ + (size_t)s * W_) = o;
        }

        // Consume ring slot holding row h0+s+2 (in flight for ~2.5 steps).
        if (s < HSTRIP - 1) finish_row(ring[s % 3], rbuf[s % 3]);
    }
}

extern "C" void kernel_launch(void* const* d_in, const int* in_sizes, int n_in,
                              void* d_out, int out_size)
{
    const float* x   = (const float*)d_in[0];   // [8,256,64,64]
    const float* ker = (const float*)d_in[1];   // [8,1,9,64,64]
    float* out = (float*)d_out;                 // [8,256,64,64]

    dim3 block(16, TY_);
    dim3 grid(N_ * (H_ / HSTRIP), C_ / (TY_ * CPT));   // (64, 16) = 1024 blocks
    ddf_kernel<<<grid, block>>>(x, ker, out);
}